// round 11
// baseline (speedup 1.0000x reference)
#include <cuda_runtime.h>
#include <cuda_fp16.h>
#include <mma.h>

#define N_NODES 40000
#define D 128
#define N_EDGES 640000
#define HASH_BITS 21
#define HASH_SIZE (1u << HASH_BITS)
#define HASH_MASK (HASH_SIZE - 1u)
#define HKEY_EMPTY 0xFFFFFFFFu
#define SCAN_B 256
#define NSCAN_BLK ((N_NODES + SCAN_B - 1) / SCAN_B)   // 157
#define LDA (D + 8)                                    // 136 halves: 16B row skew

// ---- scratch (~25 MB, no allocations allowed) ----
__device__ __align__(16) unsigned g_hash[HASH_SIZE];
__device__ int g_cnt[N_NODES];           // symmetrized incidence count
__device__ int g_off[N_NODES + 1];       // CSR offsets
__device__ int g_next[N_NODES];          // scatter cursors
__device__ unsigned g_bstate[NSCAN_BLK]; // lookback state: (incl_sum<<2)|flag
__device__ unsigned g_ent[2 * N_EDGES];  // packed: src(16) | has_rev(1)<<16 | neg(1)<<17
__device__ float g_dinv[N_NODES];
__device__ __align__(16) __half g_Zh[N_NODES * D];  // Z' = dinv .* (x @ W), fp16
__device__ __align__(16) __half g_Wh[D * D];        // 0.5*(W1+W2) fp16
__device__ float g_bias[D];                          // 0.5*(b1+b2)

__device__ __forceinline__ unsigned hash_u32(unsigned key) {
    return (key * 2654435761u) >> (32 - HASH_BITS);
}

// ---------------------------------------------------------------------------
// 1. init: hash -> EMPTY (vectorized), cnt -> 0, bstate -> 0, weights -> fp16
// ---------------------------------------------------------------------------
__global__ void k_init(const float* __restrict__ W1, const float* __restrict__ b1,
                       const float* __restrict__ W2, const float* __restrict__ b2) {
    unsigned i = blockIdx.x * blockDim.x + threadIdx.x;
    unsigned stride = gridDim.x * blockDim.x;
    uint4* h4 = reinterpret_cast<uint4*>(g_hash);
    const uint4 e4 = make_uint4(HKEY_EMPTY, HKEY_EMPTY, HKEY_EMPTY, HKEY_EMPTY);
    for (unsigned j = i; j < HASH_SIZE / 4; j += stride) h4[j] = e4;
    for (unsigned j = i; j < N_NODES; j += stride) g_cnt[j] = 0;
    if (i < NSCAN_BLK) g_bstate[i] = 0u;
    if (i < D * D) g_Wh[i] = __float2half(0.5f * (W1[i] + W2[i]));
    if (i < D) g_bias[i] = 0.5f * (b1[i] + b2[i]);
}

// ---------------------------------------------------------------------------
// 2. insert edge keys into hash set + symmetrized incidence histogram
// ---------------------------------------------------------------------------
__global__ void k_insert(const int* __restrict__ ei) {
    int e = blockIdx.x * blockDim.x + threadIdx.x;
    if (e >= N_EDGES) return;
    unsigned row = (unsigned)ei[e];
    unsigned col = (unsigned)ei[N_EDGES + e];
    unsigned key = row * (unsigned)N_NODES + col;
    unsigned h = hash_u32(key);
    while (true) {
        unsigned prev = atomicCAS(&g_hash[h], HKEY_EMPTY, key);
        if (prev == HKEY_EMPTY || prev == key) break;
        h = (h + 1u) & HASH_MASK;
    }
    atomicAdd(&g_cnt[row], 1);
    atomicAdd(&g_cnt[col], 1);
}

// ---------------------------------------------------------------------------
// 3. single-pass exclusive scan with decoupled lookback (replaces 2 kernels).
//    flag: 0 = none, 1 = aggregate available, 2 = inclusive prefix available.
//    All 157 blocks fit in one wave -> lookback cannot deadlock.
//    dinv folded in.
// ---------------------------------------------------------------------------
__global__ void k_scan() {
    __shared__ int sh[SCAN_B];
    __shared__ int s_boff;
    const int bid = blockIdx.x;
    int i = bid * SCAN_B + threadIdx.x;
    int v = (i < N_NODES) ? g_cnt[i] : 0;
    sh[threadIdx.x] = v;
    __syncthreads();
    for (int s = 1; s < SCAN_B; s <<= 1) {
        int t = (threadIdx.x >= s) ? sh[threadIdx.x - s] : 0;
        __syncthreads();
        sh[threadIdx.x] += t;
        __syncthreads();
    }
    int total = sh[SCAN_B - 1];

    if (threadIdx.x == 0) {
        if (bid == 0) {
            s_boff = 0;
            atomicExch(&g_bstate[0], ((unsigned)total << 2) | 2u);
        } else {
            atomicExch(&g_bstate[bid], ((unsigned)total << 2) | 1u);
        }
    }
    if (bid > 0 && threadIdx.x < 32) {
        const int lane = threadIdx.x;
        int prefix = 0;
        int look = bid - 1;
        while (true) {
            int idx = look - lane;                    // lane 0 = closest predecessor
            unsigned st = 0;
            if (idx >= 0) {
                do { st = atomicAdd(&g_bstate[idx], 0u); } while ((st & 3u) == 0u);
            }
            unsigned flag = st & 3u;
            unsigned msk = __ballot_sync(0xFFFFFFFFu, idx >= 0 && flag == 2u);
            if (msk) {
                int f = __ffs(msk) - 1;               // closest block with full prefix
                int contrib = (lane <= f) ? (int)(st >> 2) : 0;
                for (int o = 16; o > 0; o >>= 1)
                    contrib += __shfl_down_sync(0xFFFFFFFFu, contrib, o);
                contrib = __shfl_sync(0xFFFFFFFFu, contrib, 0);
                prefix += contrib;
                break;
            } else {
                int contrib = (idx >= 0) ? (int)(st >> 2) : 0;
                for (int o = 16; o > 0; o >>= 1)
                    contrib += __shfl_down_sync(0xFFFFFFFFu, contrib, o);
                contrib = __shfl_sync(0xFFFFFFFFu, contrib, 0);
                prefix += contrib;
                look -= 32;                            // block 0 has flag 2 -> terminates
            }
        }
        if (lane == 0) {
            s_boff = prefix;
            atomicExch(&g_bstate[bid], ((unsigned)(prefix + total) << 2) | 2u);
        }
    }
    __syncthreads();

    int excl = sh[threadIdx.x] - v + s_boff;
    if (i < N_NODES) {
        g_off[i] = excl;
        g_next[i] = excl;
        g_dinv[i] = (v > 0) ? rsqrtf(0.5f * (float)v) : 0.f;
    }
    if (i == N_NODES - 1) g_off[N_NODES] = excl + v;
}

// ---------------------------------------------------------------------------
// 4. scatter packed CSR entries (probe hash once per directed edge)
// ---------------------------------------------------------------------------
__global__ void k_scatter(const int* __restrict__ ei) {
    int e = blockIdx.x * blockDim.x + threadIdx.x;
    if (e >= N_EDGES) return;
    unsigned row = (unsigned)ei[e];
    unsigned col = (unsigned)ei[N_EDGES + e];
    unsigned rkey = col * (unsigned)N_NODES + row;
    unsigned h = hash_u32(rkey);
    unsigned v;
    while ((v = g_hash[h]) != HKEY_EMPTY && v != rkey) h = (h + 1u) & HASH_MASK;
    unsigned hr = (v == rkey) ? 0x10000u : 0u;
    int p1 = atomicAdd(&g_next[row], 1);
    g_ent[p1] = col | hr;                 // forward copy, sign +
    int p2 = atomicAdd(&g_next[col], 1);
    g_ent[p2] = row | hr | 0x20000u;      // reversed copy, sign -
}

// ---------------------------------------------------------------------------
// 5. Z' = (dinv .* x) @ W -> fp16 via wmma, padded smem (LDA=136).
//    dinv pre-scales the A tile (fp32, before fp16 convert). Accumulator
//    fragments converted to half fragments in registers (same element
//    mapping) and stored DIRECTLY to global — no smem scratch round-trip.
// ---------------------------------------------------------------------------
__global__ void __launch_bounds__(256) k_gemm_tc(const float* __restrict__ x) {
    __shared__ __align__(16) __half sA[32 * LDA];    // 8704 B
    __shared__ __align__(16) __half sB[D * LDA];     // 34816 B
    const int tid = threadIdx.x;
    const int warp = tid >> 5;
    const int block_row = blockIdx.x * 32;

    // W -> sB padded: 2048 uint4; 8/thread
    const uint4* Wh4 = reinterpret_cast<const uint4*>(g_Wh);
#pragma unroll
    for (int q = 0; q < 8; q++) {
        int idx = tid + 256 * q;
        int r = idx >> 4, c8 = idx & 15;
        *reinterpret_cast<uint4*>(sB + r * LDA + c8 * 8) = Wh4[idx];
    }

    // x tile (32x128: 1024 float4; 4/thread) scaled by dinv[row] -> fp16 sA
    const float4* X4 = reinterpret_cast<const float4*>(x);
#pragma unroll
    for (int q = 0; q < 4; q++) {
        int idx = tid + 256 * q;                       // r*32 + c4
        int r = idx >> 5, c4 = idx & 31;
        float dv = g_dinv[block_row + r];
        float4 v = X4[(size_t)block_row * 32 + idx];
        __half2* dst = reinterpret_cast<__half2*>(sA + r * LDA + c4 * 4);
        dst[0] = __floats2half2_rn(v.x * dv, v.y * dv);
        dst[1] = __floats2half2_rn(v.z * dv, v.w * dv);
    }
    __syncthreads();

    using namespace nvcuda;
    wmma::fragment<wmma::accumulator, 16, 16, 16, float> c[2];
#pragma unroll
    for (int j = 0; j < 2; j++) wmma::fill_fragment(c[j], 0.f);

    const int wm = (warp >> 2) * 16;   // 0 or 16
    const int wn = (warp & 3) * 32;    // 0,32,64,96

#pragma unroll
    for (int k = 0; k < D; k += 16) {
        wmma::fragment<wmma::matrix_a, 16, 16, 16, __half, wmma::row_major> a;
        wmma::fragment<wmma::matrix_b, 16, 16, 16, __half, wmma::row_major> b[2];
        wmma::load_matrix_sync(a, sA + wm * LDA + k, LDA);
        wmma::load_matrix_sync(b[0], sB + k * LDA + wn, LDA);
        wmma::load_matrix_sync(b[1], sB + k * LDA + wn + 16, LDA);
#pragma unroll
        for (int j = 0; j < 2; j++) wmma::mma_sync(c[j], a, b[j], c[j]);
    }

    // convert fp32 acc -> fp16 fragment in registers; store straight to global
#pragma unroll
    for (int j = 0; j < 2; j++) {
        wmma::fragment<wmma::accumulator, 16, 16, 16, __half> hc;
#pragma unroll
        for (int t = 0; t < hc.num_elements; t++) hc.x[t] = __float2half(c[j].x[t]);
        wmma::store_matrix_sync(g_Zh + (size_t)(block_row + wm) * D + wn + 16 * j,
                                hc, D, wmma::mem_row_major);
    }
}

// ---------------------------------------------------------------------------
// 6. CSR aggregation: one warp per node; Z' carries dinv[src], so weight is
//    the warp-uniform +-0.5*dinv[u]. 4-way unrolled gathers, fp32 acc.
// ---------------------------------------------------------------------------
__global__ void k_spmm_csr(float* __restrict__ out) {
    int u = blockIdx.x * (blockDim.x >> 5) + (threadIdx.x >> 5);
    int lane = threadIdx.x & 31;
    if (u >= N_NODES) return;

    int start = g_off[u];
    int end = g_off[u + 1];
    float du = 0.5f * g_dinv[u];

    const uint2* Z2 = reinterpret_cast<const uint2*>(g_Zh);
    float4 are = make_float4(0.f, 0.f, 0.f, 0.f);
    float4 aim = make_float4(0.f, 0.f, 0.f, 0.f);

    for (int base = start; base < end; base += 32) {
        int idx = base + lane;
        unsigned ent = (idx < end) ? g_ent[idx] : 0u;
        int n = min(32, end - base);
        for (int j0 = 0; j0 < n; j0 += 4) {
            int lim = n - j0;                          // warp-uniform
            unsigned ee[4];
            uint2 zz[4];
#pragma unroll
            for (int t = 0; t < 4; t++) {
                ee[t] = __shfl_sync(0xFFFFFFFFu, ent, j0 + t);
                if (t < lim) zz[t] = Z2[(size_t)(ee[t] & 0xFFFFu) * 32 + lane];
            }
#pragma unroll
            for (int t = 0; t < 4; t++) {
                if (t < lim) {
                    __half2 h0 = *reinterpret_cast<__half2*>(&zz[t].x);
                    __half2 h1 = *reinterpret_cast<__half2*>(&zz[t].y);
                    float2 f0 = __half22float2(h0);
                    float2 f1 = __half22float2(h1);
                    if (ee[t] & 0x10000u) {
                        are.x = fmaf(du, f0.x, are.x); are.y = fmaf(du, f0.y, are.y);
                        are.z = fmaf(du, f1.x, are.z); are.w = fmaf(du, f1.y, are.w);
                    } else {
                        float s = (ee[t] & 0x20000u) ? -du : du;
                        aim.x = fmaf(s, f0.x, aim.x); aim.y = fmaf(s, f0.y, aim.y);
                        aim.z = fmaf(s, f1.x, aim.z); aim.w = fmaf(s, f1.y, aim.w);
                    }
                }
            }
        }
    }

    float4 bias = reinterpret_cast<const float4*>(g_bias)[lane];
    float4* O4 = reinterpret_cast<float4*>(out);
    O4[(size_t)u * 64 + lane] =
        make_float4(are.x + bias.x, are.y + bias.y, are.z + bias.z, are.w + bias.w);
    O4[(size_t)u * 64 + 32 + lane] =
        make_float4(aim.x + bias.x, aim.y + bias.y, aim.z + bias.z, aim.w + bias.w);
}

// ---------------------------------------------------------------------------
extern "C" void kernel_launch(void* const* d_in, const int* in_sizes, int n_in,
                              void* d_out, int out_size) {
    const float* x  = (const float*)d_in[0];
    const int*   ei = (const int*)d_in[1];
    const float* W1 = (const float*)d_in[2];
    const float* b1 = (const float*)d_in[3];
    const float* W2 = (const float*)d_in[4];
    const float* b2 = (const float*)d_in[5];
    float* out = (float*)d_out;

    k_init<<<512, 256>>>(W1, b1, W2, b2);
    k_insert<<<(N_EDGES + 255) / 256, 256>>>(ei);
    k_scan<<<NSCAN_BLK, SCAN_B>>>();
    k_scatter<<<(N_EDGES + 255) / 256, 256>>>(ei);
    k_gemm_tc<<<N_NODES / 32, 256>>>(x);
    k_spmm_csr<<<(N_NODES + 15) / 16, 512>>>(out);
}

// round 12
// speedup vs baseline: 1.0246x; 1.0246x over previous
#include <cuda_runtime.h>
#include <cuda_fp16.h>
#include <mma.h>

#define N_NODES 40000
#define D 128
#define N_EDGES 640000
#define HASH_BITS 21
#define HASH_SIZE (1u << HASH_BITS)
#define HASH_MASK (HASH_SIZE - 1u)
#define HKEY_EMPTY 0xFFFFFFFFu
#define SCAN_B 256
#define NSCAN_BLK ((N_NODES + SCAN_B - 1) / SCAN_B)   // 157
#define LDA (D + 8)                                    // 136 halves: 16B row skew

// ---- scratch (~27 MB, no allocations allowed) ----
__device__ __align__(16) unsigned g_hash[HASH_SIZE];
__device__ int g_cnt[N_NODES];           // symmetrized incidence count
__device__ int g_off[N_NODES + 1];       // CSR offsets
__device__ uint2 g_slot[N_EDGES];        // per-edge (p1, p2) cursor values from insert
__device__ unsigned g_bstate[NSCAN_BLK]; // lookback state: (incl_sum<<2)|flag
__device__ unsigned g_ent[2 * N_EDGES];  // packed: src(16) | has_rev(1)<<16 | neg(1)<<17
__device__ float g_dinv[N_NODES];
__device__ __align__(16) __half g_Zh[N_NODES * D];  // Z' = dinv .* (x @ W), fp16
__device__ __align__(16) __half g_Wh[D * D];        // 0.5*(W1+W2) fp16
__device__ float g_bias[D];                          // 0.5*(b1+b2)

__device__ __forceinline__ unsigned hash_u32(unsigned key) {
    return (key * 2654435761u) >> (32 - HASH_BITS);
}

// ---------------------------------------------------------------------------
// 1. init: hash -> EMPTY (vectorized), cnt -> 0, bstate -> 0, weights -> fp16
// ---------------------------------------------------------------------------
__global__ void k_init(const float* __restrict__ W1, const float* __restrict__ b1,
                       const float* __restrict__ W2, const float* __restrict__ b2) {
    unsigned i = blockIdx.x * blockDim.x + threadIdx.x;
    unsigned stride = gridDim.x * blockDim.x;
    uint4* h4 = reinterpret_cast<uint4*>(g_hash);
    const uint4 e4 = make_uint4(HKEY_EMPTY, HKEY_EMPTY, HKEY_EMPTY, HKEY_EMPTY);
    for (unsigned j = i; j < HASH_SIZE / 4; j += stride) h4[j] = e4;
    for (unsigned j = i; j < N_NODES; j += stride) g_cnt[j] = 0;
    if (i < NSCAN_BLK) g_bstate[i] = 0u;
    if (i < D * D) g_Wh[i] = __float2half(0.5f * (W1[i] + W2[i]));
    if (i < D) g_bias[i] = 0.5f * (b1[i] + b2[i]);
}

// ---------------------------------------------------------------------------
// 2. insert: hash-insert edge key + histogram. The atomicAdd RETURN VALUES are
//    the within-node slot indices — persist them so scatter needs no atomics.
// ---------------------------------------------------------------------------
__global__ void k_insert(const int* __restrict__ ei) {
    int e = blockIdx.x * blockDim.x + threadIdx.x;
    if (e >= N_EDGES) return;
    unsigned row = (unsigned)ei[e];
    unsigned col = (unsigned)ei[N_EDGES + e];
    unsigned key = row * (unsigned)N_NODES + col;
    unsigned h = hash_u32(key);
    while (true) {
        unsigned prev = atomicCAS(&g_hash[h], HKEY_EMPTY, key);
        if (prev == HKEY_EMPTY || prev == key) break;
        h = (h + 1u) & HASH_MASK;
    }
    unsigned p1 = (unsigned)atomicAdd(&g_cnt[row], 1);
    unsigned p2 = (unsigned)atomicAdd(&g_cnt[col], 1);
    g_slot[e] = make_uint2(p1, p2);       // coalesced 8B write
}

// ---------------------------------------------------------------------------
// 3. single-pass exclusive scan with decoupled lookback. dinv folded in.
// ---------------------------------------------------------------------------
__global__ void k_scan() {
    __shared__ int sh[SCAN_B];
    __shared__ int s_boff;
    const int bid = blockIdx.x;
    int i = bid * SCAN_B + threadIdx.x;
    int v = (i < N_NODES) ? g_cnt[i] : 0;
    sh[threadIdx.x] = v;
    __syncthreads();
    for (int s = 1; s < SCAN_B; s <<= 1) {
        int t = (threadIdx.x >= s) ? sh[threadIdx.x - s] : 0;
        __syncthreads();
        sh[threadIdx.x] += t;
        __syncthreads();
    }
    int total = sh[SCAN_B - 1];

    if (threadIdx.x == 0) {
        if (bid == 0) {
            s_boff = 0;
            atomicExch(&g_bstate[0], ((unsigned)total << 2) | 2u);
        } else {
            atomicExch(&g_bstate[bid], ((unsigned)total << 2) | 1u);
        }
    }
    if (bid > 0 && threadIdx.x < 32) {
        const int lane = threadIdx.x;
        int prefix = 0;
        int look = bid - 1;
        while (true) {
            int idx = look - lane;                    // lane 0 = closest predecessor
            unsigned st = 0;
            if (idx >= 0) {
                do { st = atomicAdd(&g_bstate[idx], 0u); } while ((st & 3u) == 0u);
            }
            unsigned flag = st & 3u;
            unsigned msk = __ballot_sync(0xFFFFFFFFu, idx >= 0 && flag == 2u);
            if (msk) {
                int f = __ffs(msk) - 1;               // closest block with full prefix
                int contrib = (lane <= f) ? (int)(st >> 2) : 0;
                for (int o = 16; o > 0; o >>= 1)
                    contrib += __shfl_down_sync(0xFFFFFFFFu, contrib, o);
                contrib = __shfl_sync(0xFFFFFFFFu, contrib, 0);
                prefix += contrib;
                break;
            } else {
                int contrib = (idx >= 0) ? (int)(st >> 2) : 0;
                for (int o = 16; o > 0; o >>= 1)
                    contrib += __shfl_down_sync(0xFFFFFFFFu, contrib, o);
                contrib = __shfl_sync(0xFFFFFFFFu, contrib, 0);
                prefix += contrib;
                look -= 32;                            // block 0 has flag 2 -> terminates
            }
        }
        if (lane == 0) {
            s_boff = prefix;
            atomicExch(&g_bstate[bid], ((unsigned)(prefix + total) << 2) | 2u);
        }
    }
    __syncthreads();

    int excl = sh[threadIdx.x] - v + s_boff;
    if (i < N_NODES) {
        g_off[i] = excl;
        g_dinv[i] = (v > 0) ? rsqrtf(0.5f * (float)v) : 0.f;
    }
    if (i == N_NODES - 1) g_off[N_NODES] = excl + v;
}

// ---------------------------------------------------------------------------
// 4. scatter: NO atomics — placement = g_off[node] + saved cursor. Slots are
//    collision-free (cursor values are a permutation of 0..cnt-1 per node).
//    Hash probe sets has_rev (2*pi*Q = pi/2: hr ? real : +-imag).
// ---------------------------------------------------------------------------
__global__ void k_scatter(const int* __restrict__ ei) {
    int e = blockIdx.x * blockDim.x + threadIdx.x;
    if (e >= N_EDGES) return;
    unsigned row = (unsigned)ei[e];
    unsigned col = (unsigned)ei[N_EDGES + e];
    uint2 sl = g_slot[e];
    unsigned rkey = col * (unsigned)N_NODES + row;
    unsigned h = hash_u32(rkey);
    unsigned v;
    while ((v = g_hash[h]) != HKEY_EMPTY && v != rkey) h = (h + 1u) & HASH_MASK;
    unsigned hr = (v == rkey) ? 0x10000u : 0u;
    g_ent[g_off[row] + sl.x] = col | hr;              // forward copy, sign +
    g_ent[g_off[col] + sl.y] = row | hr | 0x20000u;   // reversed copy, sign -
}

// ---------------------------------------------------------------------------
// 5. Z' = (dinv .* x) @ W -> fp16 via wmma, padded smem (LDA=136), direct
//    fragment->global epilogue (fp32 acc converted to half in registers).
// ---------------------------------------------------------------------------
__global__ void __launch_bounds__(256) k_gemm_tc(const float* __restrict__ x) {
    __shared__ __align__(16) __half sA[32 * LDA];    // 8704 B
    __shared__ __align__(16) __half sB[D * LDA];     // 34816 B
    const int tid = threadIdx.x;
    const int warp = tid >> 5;
    const int block_row = blockIdx.x * 32;

    // W -> sB padded: 2048 uint4; 8/thread
    const uint4* Wh4 = reinterpret_cast<const uint4*>(g_Wh);
#pragma unroll
    for (int q = 0; q < 8; q++) {
        int idx = tid + 256 * q;
        int r = idx >> 4, c8 = idx & 15;
        *reinterpret_cast<uint4*>(sB + r * LDA + c8 * 8) = Wh4[idx];
    }

    // x tile (32x128: 1024 float4; 4/thread) scaled by dinv[row] -> fp16 sA
    const float4* X4 = reinterpret_cast<const float4*>(x);
#pragma unroll
    for (int q = 0; q < 4; q++) {
        int idx = tid + 256 * q;                       // r*32 + c4
        int r = idx >> 5, c4 = idx & 31;
        float dv = g_dinv[block_row + r];
        float4 v = X4[(size_t)block_row * 32 + idx];
        __half2* dst = reinterpret_cast<__half2*>(sA + r * LDA + c4 * 4);
        dst[0] = __floats2half2_rn(v.x * dv, v.y * dv);
        dst[1] = __floats2half2_rn(v.z * dv, v.w * dv);
    }
    __syncthreads();

    using namespace nvcuda;
    wmma::fragment<wmma::accumulator, 16, 16, 16, float> c[2];
#pragma unroll
    for (int j = 0; j < 2; j++) wmma::fill_fragment(c[j], 0.f);

    const int wm = (warp >> 2) * 16;   // 0 or 16
    const int wn = (warp & 3) * 32;    // 0,32,64,96

#pragma unroll
    for (int k = 0; k < D; k += 16) {
        wmma::fragment<wmma::matrix_a, 16, 16, 16, __half, wmma::row_major> a;
        wmma::fragment<wmma::matrix_b, 16, 16, 16, __half, wmma::row_major> b[2];
        wmma::load_matrix_sync(a, sA + wm * LDA + k, LDA);
        wmma::load_matrix_sync(b[0], sB + k * LDA + wn, LDA);
        wmma::load_matrix_sync(b[1], sB + k * LDA + wn + 16, LDA);
#pragma unroll
        for (int j = 0; j < 2; j++) wmma::mma_sync(c[j], a, b[j], c[j]);
    }

    // convert fp32 acc -> fp16 fragment in registers; store straight to global
#pragma unroll
    for (int j = 0; j < 2; j++) {
        wmma::fragment<wmma::accumulator, 16, 16, 16, __half> hc;
#pragma unroll
        for (int t = 0; t < hc.num_elements; t++) hc.x[t] = __float2half(c[j].x[t]);
        wmma::store_matrix_sync(g_Zh + (size_t)(block_row + wm) * D + wn + 16 * j,
                                hc, D, wmma::mem_row_major);
    }
}

// ---------------------------------------------------------------------------
// 6. CSR aggregation: one warp per node; Z' carries dinv[src], so weight is
//    the warp-uniform +-0.5*dinv[u]. 4-way unrolled gathers, fp32 acc.
// ---------------------------------------------------------------------------
__global__ void k_spmm_csr(float* __restrict__ out) {
    int u = blockIdx.x * (blockDim.x >> 5) + (threadIdx.x >> 5);
    int lane = threadIdx.x & 31;
    if (u >= N_NODES) return;

    int start = g_off[u];
    int end = g_off[u + 1];
    float du = 0.5f * g_dinv[u];

    const uint2* Z2 = reinterpret_cast<const uint2*>(g_Zh);
    float4 are = make_float4(0.f, 0.f, 0.f, 0.f);
    float4 aim = make_float4(0.f, 0.f, 0.f, 0.f);

    for (int base = start; base < end; base += 32) {
        int idx = base + lane;
        unsigned ent = (idx < end) ? g_ent[idx] : 0u;
        int n = min(32, end - base);
        for (int j0 = 0; j0 < n; j0 += 4) {
            int lim = n - j0;                          // warp-uniform
            unsigned ee[4];
            uint2 zz[4];
#pragma unroll
            for (int t = 0; t < 4; t++) {
                ee[t] = __shfl_sync(0xFFFFFFFFu, ent, j0 + t);
                if (t < lim) zz[t] = Z2[(size_t)(ee[t] & 0xFFFFu) * 32 + lane];
            }
#pragma unroll
            for (int t = 0; t < 4; t++) {
                if (t < lim) {
                    __half2 h0 = *reinterpret_cast<__half2*>(&zz[t].x);
                    __half2 h1 = *reinterpret_cast<__half2*>(&zz[t].y);
                    float2 f0 = __half22float2(h0);
                    float2 f1 = __half22float2(h1);
                    if (ee[t] & 0x10000u) {
                        are.x = fmaf(du, f0.x, are.x); are.y = fmaf(du, f0.y, are.y);
                        are.z = fmaf(du, f1.x, are.z); are.w = fmaf(du, f1.y, are.w);
                    } else {
                        float s = (ee[t] & 0x20000u) ? -du : du;
                        aim.x = fmaf(s, f0.x, aim.x); aim.y = fmaf(s, f0.y, aim.y);
                        aim.z = fmaf(s, f1.x, aim.z); aim.w = fmaf(s, f1.y, aim.w);
                    }
                }
            }
        }
    }

    float4 bias = reinterpret_cast<const float4*>(g_bias)[lane];
    float4* O4 = reinterpret_cast<float4*>(out);
    O4[(size_t)u * 64 + lane] =
        make_float4(are.x + bias.x, are.y + bias.y, are.z + bias.z, are.w + bias.w);
    O4[(size_t)u * 64 + 32 + lane] =
        make_float4(aim.x + bias.x, aim.y + bias.y, aim.z + bias.z, aim.w + bias.w);
}

// ---------------------------------------------------------------------------
extern "C" void kernel_launch(void* const* d_in, const int* in_sizes, int n_in,
                              void* d_out, int out_size) {
    const float* x  = (const float*)d_in[0];
    const int*   ei = (const int*)d_in[1];
    const float* W1 = (const float*)d_in[2];
    const float* b1 = (const float*)d_in[3];
    const float* W2 = (const float*)d_in[4];
    const float* b2 = (const float*)d_in[5];
    float* out = (float*)d_out;

    k_init<<<512, 256>>>(W1, b1, W2, b2);
    k_insert<<<(N_EDGES + 255) / 256, 256>>>(ei);
    k_scan<<<NSCAN_BLK, SCAN_B>>>();
    k_scatter<<<(N_EDGES + 255) / 256, 256>>>(ei);
    k_gemm_tc<<<N_NODES / 32, 256>>>(x);
    k_spmm_csr<<<(N_NODES + 15) / 16, 512>>>(out);
}